// round 6
// baseline (speedup 1.0000x reference)
#include <cuda_runtime.h>
#include <math.h>
#include <mma.h>

using namespace nvcuda;

// Problem constants
constexpr int cB   = 32;
constexpr int cN   = 256;
constexpr int cF   = 300;
constexpr int cO   = 256;
constexpr int cH   = 8;
constexpr int cHO  = 2048;   // H*O
constexpr int cOUT = 512;
#define NEGV (-9e15f)

// ---------------- scratch (device globals; no allocation) ----------------
__device__ float g_x    [cB * cN * cF];                 // (B*N, F)
__device__ float g_Wh   [(size_t)cH * cB * cN * cO];    // (H,B,N,O)
__device__ float g_e1   [cH * cB * cN];
__device__ float g_e2   [cH * cB * cN];
__device__ float g_attn [(size_t)cH * cB * cN * cN];    // (H,B,N,N)
__device__ float g_hHB  [(size_t)cH * cB * cN * cO];    // (H,B,N,O)
__device__ float g_h1   [(size_t)cB * cN * cHO];        // (B,N,H*O)
__device__ float g_Wh2  [(size_t)cB * cN * cOUT];       // (B,N,OUT)
__device__ float g_e1b  [cB * cN];
__device__ float g_e2b  [cB * cN];
__device__ float g_attn2[(size_t)cB * cN * cN];         // (B,N,N)
__device__ float g_tmp  [(size_t)cB * cN * cOUT];       // pre-ELU output

// ---------------- embedding gather (float4) ----------------
__global__ void gather_kernel(const int* __restrict__ fea,
                              const float* __restrict__ embed) {
    int i4 = blockIdx.x * blockDim.x + threadIdx.x;
    constexpr int F4 = cF / 4;  // 75
    if (i4 >= cB * cN * F4) return;
    int f4 = i4 % F4;
    int bn = i4 / F4;
    const float4* src = (const float4*)(embed + (size_t)fea[bn] * cF);
    ((float4*)g_x)[(size_t)bn * F4 + f4] = src[f4];
}

// ---------------- 3xTF32 tensor-core batched GEMM: C = A @ B ----------------
// A: (M,K) row-major, B: (K,Nc) row-major, C: (M,Nc) row-major (fp32).
// 128x64 block tile, BK=16, 256 threads = 8 warps (4 row x 2 col),
// warp tile 32x32 = 2x2 wmma m16n16k8 tiles.
// Error-split: x = hi + lo (tf32), C += Ah*Bl + Al*Bh + Ah*Bh  -> ~fp32 accuracy.
__device__ __forceinline__ void split_tf32(float v, float& hi, float& lo) {
    hi = wmma::__float_to_tf32(v);
    lo = wmma::__float_to_tf32(v - hi);
}

__global__ __launch_bounds__(256, 2)
void gemm_tc_kernel(const float* __restrict__ A, const float* __restrict__ Bm,
                    float* __restrict__ C,
                    int M, int Nc, int K,
                    long long sA, long long sB, long long sC) {
    constexpr int BM = 128, BN = 64, BK = 16;
    __shared__ float As_hi[BM][BK];
    __shared__ float As_lo[BM][BK];
    __shared__ float Bs_hi[BK][BN];
    __shared__ float Bs_lo[BK][BN];

    int batch = blockIdx.z;
    A  += (long long)batch * sA;
    Bm += (long long)batch * sB;
    C  += (long long)batch * sC;

    int m0 = blockIdx.y * BM;
    int n0 = blockIdx.x * BN;
    int t  = threadIdx.x;
    int warp = t >> 5;
    int wr = warp >> 1;   // 0..3
    int wc = warp & 1;    // 0..1
    int wm = wr * 32;     // warp row offset in tile
    int wn = wc * 32;     // warp col offset in tile

    wmma::fragment<wmma::accumulator, 16, 16, 8, float> acc[2][2];
    #pragma unroll
    for (int i = 0; i < 2; i++)
        #pragma unroll
        for (int j = 0; j < 2; j++)
            wmma::fill_fragment(acc[i][j], 0.0f);

    for (int k0 = 0; k0 < K; k0 += BK) {
        // --- load A tile 128x16 (scalar, K-tail guarded) ---
        #pragma unroll
        for (int i = 0; i < 8; i++) {
            int idx = t + i * 256;
            int r = idx >> 4, c = idx & 15;
            float v = 0.f;
            if (k0 + c < K) v = A[(long long)(m0 + r) * K + (k0 + c)];
            float hi, lo; split_tf32(v, hi, lo);
            As_hi[r][c] = hi; As_lo[r][c] = lo;
        }
        // --- load B tile 16x64 (float4, K-tail guarded) ---
        {
            int r = t >> 4, c4 = t & 15;
            float4 v = make_float4(0.f, 0.f, 0.f, 0.f);
            if (k0 + r < K)
                v = *(const float4*)(Bm + (long long)(k0 + r) * Nc + n0 + c4 * 4);
            float hi, lo;
            split_tf32(v.x, hi, lo); Bs_hi[r][c4*4+0] = hi; Bs_lo[r][c4*4+0] = lo;
            split_tf32(v.y, hi, lo); Bs_hi[r][c4*4+1] = hi; Bs_lo[r][c4*4+1] = lo;
            split_tf32(v.z, hi, lo); Bs_hi[r][c4*4+2] = hi; Bs_lo[r][c4*4+2] = lo;
            split_tf32(v.w, hi, lo); Bs_hi[r][c4*4+3] = hi; Bs_lo[r][c4*4+3] = lo;
        }
        __syncthreads();

        #pragma unroll
        for (int ks = 0; ks < 2; ks++) {
            wmma::fragment<wmma::matrix_a, 16, 16, 8, wmma::precision::tf32, wmma::row_major> ah[2], al[2];
            wmma::fragment<wmma::matrix_b, 16, 16, 8, wmma::precision::tf32, wmma::row_major> bh[2], bl[2];
            #pragma unroll
            for (int i = 0; i < 2; i++) {
                wmma::load_matrix_sync(ah[i], &As_hi[wm + i * 16][ks * 8], BK);
                wmma::load_matrix_sync(al[i], &As_lo[wm + i * 16][ks * 8], BK);
            }
            #pragma unroll
            for (int j = 0; j < 2; j++) {
                wmma::load_matrix_sync(bh[j], &Bs_hi[ks * 8][wn + j * 16], BN);
                wmma::load_matrix_sync(bl[j], &Bs_lo[ks * 8][wn + j * 16], BN);
            }
            #pragma unroll
            for (int i = 0; i < 2; i++)
                #pragma unroll
                for (int j = 0; j < 2; j++) {
                    wmma::mma_sync(acc[i][j], ah[i], bl[j], acc[i][j]);
                    wmma::mma_sync(acc[i][j], al[i], bh[j], acc[i][j]);
                    wmma::mma_sync(acc[i][j], ah[i], bh[j], acc[i][j]);
                }
        }
        __syncthreads();
    }

    #pragma unroll
    for (int i = 0; i < 2; i++)
        #pragma unroll
        for (int j = 0; j < 2; j++)
            wmma::store_matrix_sync(&C[(long long)(m0 + wm + i * 16) * Nc + (n0 + wn + j * 16)],
                                    acc[i][j], Nc, wmma::mem_row_major);
}

// ---------------- attention coefficients: e1/e2 dot products ----------------
__global__ void attn_coef_kernel(const float* __restrict__ Wh,
                                 const float* __restrict__ a,
                                 float* __restrict__ e1, float* __restrict__ e2,
                                 int Of, int rowsPerHead, int totalRows) {
    int gw = (blockIdx.x * blockDim.x + threadIdx.x) >> 5;
    if (gw >= totalRows) return;
    int lane = threadIdx.x & 31;
    int h = gw / rowsPerHead;
    const float* w  = Wh + (size_t)gw * Of;
    const float* a1 = a + (size_t)h * 2 * Of;
    const float* a2 = a1 + Of;
    float s1 = 0.f, s2 = 0.f;
    for (int o = lane; o < Of; o += 32) {
        float v = w[o];
        s1 = fmaf(v, a1[o], s1);
        s2 = fmaf(v, a2[o], s2);
    }
    #pragma unroll
    for (int off = 16; off; off >>= 1) {
        s1 += __shfl_xor_sync(0xffffffffu, s1, off);
        s2 += __shfl_xor_sync(0xffffffffu, s2, off);
    }
    if (lane == 0) { e1[gw] = s1; e2[gw] = s2; }
}

// ---------------- masked leaky-relu softmax: one WARP per row of 256 ----------------
// Row layout: (HB, N). adj is (B,N,N): b = hb % cB, n = row % cN.
__global__ void softmax_kernel(const float* __restrict__ e1,
                               const float* __restrict__ e2,
                               const int* __restrict__ adj,
                               float* __restrict__ attn,
                               int totalRows) {
    int gw = (blockIdx.x * blockDim.x + threadIdx.x) >> 5;
    if (gw >= totalRows) return;
    int lane = threadIdx.x & 31;
    int hb = gw >> 8;           // row / cN
    int n  = gw & 255;
    int b  = hb & (cB - 1);     // cB = 32

    const int4*   adjRow = (const int4*)(adj + ((size_t)b * cN + n) * cN);
    const float4* e2Row  = (const float4*)(e2 + (size_t)hb * cN);
    float e1v = e1[gw];

    float v[8];
    float vmax = -INFINITY;
    #pragma unroll
    for (int jj = 0; jj < 2; jj++) {
        int i4 = lane + 32 * jj;
        int4   a4 = adjRow[i4];
        float4 e4 = e2Row[i4];
        const float* ep = (const float*)&e4;
        const int*   ap = (const int*)&a4;
        #pragma unroll
        for (int c = 0; c < 4; c++) {
            float x = e1v + ep[c];
            x = x > 0.f ? x : 0.2f * x;
            if (ap[c] <= 0) x = NEGV;
            v[jj * 4 + c] = x;
            vmax = fmaxf(vmax, x);
        }
    }
    #pragma unroll
    for (int off = 16; off; off >>= 1)
        vmax = fmaxf(vmax, __shfl_xor_sync(0xffffffffu, vmax, off));

    float s = 0.f;
    #pragma unroll
    for (int k = 0; k < 8; k++) { v[k] = expf(v[k] - vmax); s += v[k]; }
    #pragma unroll
    for (int off = 16; off; off >>= 1)
        s += __shfl_xor_sync(0xffffffffu, s, off);
    float inv = 1.f / s;

    float4* outRow = (float4*)(attn + (size_t)gw * cN);
    #pragma unroll
    for (int jj = 0; jj < 2; jj++) {
        int i4 = lane + 32 * jj;
        outRow[i4] = make_float4(v[jj*4+0]*inv, v[jj*4+1]*inv, v[jj*4+2]*inv, v[jj*4+3]*inv);
    }
}

// ---------------- head merge: elu + transpose (H,B,N,O)->(B,N,H*O) + mask (float4) ----------------
__global__ void head_merge_kernel(const float* __restrict__ mask) {
    int i4 = blockIdx.x * blockDim.x + threadIdx.x;
    if (i4 >= cH * cB * cN * cO / 4) return;
    int o4  = i4 & 63;            // cO/4 = 64
    int rem = i4 >> 6;
    int n   = rem & (cN - 1); rem >>= 8;
    int b   = rem & (cB - 1);
    int h   = rem >> 5;
    float4 val = ((const float4*)g_hHB)[i4];
    float mk = mask[b * cN + n];
    float* vp = (float*)&val;
    #pragma unroll
    for (int c = 0; c < 4; c++) {
        float v = vp[c];
        v = v > 0.f ? v : expm1f(v);
        vp[c] = v * mk;
    }
    ((float4*)g_h1)[((size_t)(b * cN + n)) * (cHO / 4) + h * (cO / 4) + o4] = val;
}

// ---------------- final: out = elu(tmp * mask) (float4) ----------------
__global__ void final_elu_kernel(const float* __restrict__ mask,
                                 float* __restrict__ out) {
    int i4 = blockIdx.x * blockDim.x + threadIdx.x;
    if (i4 >= cB * cN * cOUT / 4) return;
    float4 val = ((const float4*)g_tmp)[i4];
    float mk = mask[i4 >> 7];     // (cOUT/4) = 128
    float* vp = (float*)&val;
    #pragma unroll
    for (int c = 0; c < 4; c++) {
        float v = vp[c] * mk;
        vp[c] = v > 0.f ? v : expm1f(v);
    }
    ((float4*)out)[i4] = val;
}

// ---------------- launch ----------------
extern "C" void kernel_launch(void* const* d_in, const int* in_sizes, int n_in,
                              void* d_out, int out_size) {
    const int*   fea    = (const int*)  d_in[0];
    const int*   adj    = (const int*)  d_in[1];
    const float* mask   = (const float*)d_in[2];
    const float* embed  = (const float*)d_in[3];
    const float* Wheads = (const float*)d_in[4];
    const float* aheads = (const float*)d_in[5];
    const float* Wout   = (const float*)d_in[6];
    const float* aout   = (const float*)d_in[7];
    float* out = (float*)d_out;

    float *px, *pWh, *pe1, *pe2, *pattn, *phHB, *ph1, *pWh2, *pe1b, *pe2b, *pattn2, *ptmp;
    cudaGetSymbolAddress((void**)&px,     g_x);
    cudaGetSymbolAddress((void**)&pWh,    g_Wh);
    cudaGetSymbolAddress((void**)&pe1,    g_e1);
    cudaGetSymbolAddress((void**)&pe2,    g_e2);
    cudaGetSymbolAddress((void**)&pattn,  g_attn);
    cudaGetSymbolAddress((void**)&phHB,   g_hHB);
    cudaGetSymbolAddress((void**)&ph1,    g_h1);
    cudaGetSymbolAddress((void**)&pWh2,   g_Wh2);
    cudaGetSymbolAddress((void**)&pe1b,   g_e1b);
    cudaGetSymbolAddress((void**)&pe2b,   g_e2b);
    cudaGetSymbolAddress((void**)&pattn2, g_attn2);
    cudaGetSymbolAddress((void**)&ptmp,   g_tmp);

    // 1) embedding gather
    gather_kernel<<<(cB * cN * (cF / 4) + 255) / 256, 256>>>(fea, embed);

    // 2) Wh = x @ W_heads[h]   -> (H,B,N,O)
    gemm_tc_kernel<<<dim3(cO / 64, (cB * cN) / 128, cH), 256>>>(
        px, Wheads, pWh, cB * cN, cO, cF,
        0LL, (long long)cF * cO, (long long)cB * cN * cO);

    // 3) e1/e2 per (h,b,n)
    attn_coef_kernel<<<(cH * cB * cN * 32 + 255) / 256, 256>>>(
        pWh, aheads, pe1, pe2, cO, cB * cN, cH * cB * cN);

    // 4) masked leaky softmax -> attn (H,B,N,N)
    softmax_kernel<<<(cH * cB * cN * 32 + 255) / 256, 256>>>(pe1, pe2, adj, pattn, cH * cB * cN);

    // 5) hHB = attn @ Wh  (batched over H*B)
    gemm_tc_kernel<<<dim3(cO / 64, cN / 128, cH * cB), 256>>>(
        pattn, pWh, phHB, cN, cO, cN,
        (long long)cN * cN, (long long)cN * cO, (long long)cN * cO);

    // 6) elu + head-concat transpose + mask -> h1 (B,N,H*O)
    head_merge_kernel<<<(cH * cB * cN * cO / 4 + 255) / 256, 256>>>(mask);

    // 7) Wh2 = h1 @ W_out  -> (B,N,OUT)
    gemm_tc_kernel<<<dim3(cOUT / 64, (cB * cN) / 128, 1), 256>>>(
        ph1, Wout, pWh2, cB * cN, cOUT, cHO, 0LL, 0LL, 0LL);

    // 8) e1b/e2b per (b,n)
    attn_coef_kernel<<<(cB * cN * 32 + 255) / 256, 256>>>(
        pWh2, aout, pe1b, pe2b, cOUT, cB * cN, cB * cN);

    // 9) softmax -> attn2 (B,N,N)
    softmax_kernel<<<(cB * cN * 32 + 255) / 256, 256>>>(pe1b, pe2b, adj, pattn2, cB * cN);

    // 10) tmp = attn2 @ Wh2 (batched over B)
    gemm_tc_kernel<<<dim3(cOUT / 64, cN / 128, cB), 256>>>(
        pattn2, pWh2, ptmp, cN, cOUT, cN,
        (long long)cN * cN, (long long)cN * cOUT, (long long)cN * cOUT);

    // 11) out = elu(tmp * mask)
    final_elu_kernel<<<(cB * cN * cOUT / 4 + 255) / 256, 256>>>(mask, out);
}

// round 7
// speedup vs baseline: 1.0011x; 1.0011x over previous
#include <cuda_runtime.h>
#include <math.h>
#include <mma.h>

using namespace nvcuda;

// Problem constants
constexpr int cB   = 32;
constexpr int cN   = 256;
constexpr int cF   = 300;
constexpr int cO   = 256;
constexpr int cH   = 8;
constexpr int cHO  = 2048;   // H*O
constexpr int cOUT = 512;
#define NEGV (-9e15f)

// ---------------- scratch (device globals; no allocation) ----------------
__device__ float g_x    [cB * cN * cF];                 // (B*N, F)
__device__ float g_Wh   [(size_t)cH * cB * cN * cO];    // (H,B,N,O)
__device__ float g_e1   [cH * cB * cN];
__device__ float g_e2   [cH * cB * cN];
__device__ float g_attn [(size_t)cH * cB * cN * cN];    // (H,B,N,N)
__device__ float g_hHB  [(size_t)cH * cB * cN * cO];    // (H,B,N,O)
__device__ float g_h1   [(size_t)cB * cN * cHO];        // (B,N,H*O)
__device__ float g_Wh2  [(size_t)cB * cN * cOUT];       // (B,N,OUT)
__device__ float g_e1b  [cB * cN];
__device__ float g_e2b  [cB * cN];
__device__ float g_attn2[(size_t)cB * cN * cN];         // (B,N,N)
__device__ float g_tmp  [(size_t)cB * cN * cOUT];       // pre-ELU output

// ---------------- embedding gather (float4) ----------------
__global__ void gather_kernel(const int* __restrict__ fea,
                              const float* __restrict__ embed) {
    int i4 = blockIdx.x * blockDim.x + threadIdx.x;
    constexpr int F4 = cF / 4;  // 75
    if (i4 >= cB * cN * F4) return;
    int f4 = i4 % F4;
    int bn = i4 / F4;
    const float4* src = (const float4*)(embed + (size_t)fea[bn] * cF);
    ((float4*)g_x)[(size_t)bn * F4 + f4] = src[f4];
}

// ---------------- 3xTF32 tensor-core batched GEMM: C = A @ B ----------------
// A: (M,K) row-major, B: (K,Nc) row-major, C: (M,Nc) row-major (fp32).
// 128x64 block tile, BK=16, 256 threads = 8 warps (4 row x 2 col),
// warp tile 32x32 = 2x2 wmma m16n16k8 tiles.
// Error-split: x = hi + lo (tf32), C += Ah*Bl + Al*Bh + Ah*Bh  -> ~fp32 accuracy.
__device__ __forceinline__ void split_tf32(float v, float& hi, float& lo) {
    hi = wmma::__float_to_tf32(v);
    lo = wmma::__float_to_tf32(v - hi);
}

__global__ __launch_bounds__(256, 2)
void gemm_tc_kernel(const float* __restrict__ A, const float* __restrict__ Bm,
                    float* __restrict__ C,
                    int M, int Nc, int K,
                    long long sA, long long sB, long long sC) {
    constexpr int BM = 128, BN = 64, BK = 16;
    __shared__ float As_hi[BM][BK];
    __shared__ float As_lo[BM][BK];
    __shared__ float Bs_hi[BK][BN];
    __shared__ float Bs_lo[BK][BN];

    int batch = blockIdx.z;
    A  += (long long)batch * sA;
    Bm += (long long)batch * sB;
    C  += (long long)batch * sC;

    int m0 = blockIdx.y * BM;
    int n0 = blockIdx.x * BN;
    int t  = threadIdx.x;
    int warp = t >> 5;
    int wr = warp >> 1;   // 0..3
    int wc = warp & 1;    // 0..1
    int wm = wr * 32;     // warp row offset in tile
    int wn = wc * 32;     // warp col offset in tile

    wmma::fragment<wmma::accumulator, 16, 16, 8, float> acc[2][2];
    #pragma unroll
    for (int i = 0; i < 2; i++)
        #pragma unroll
        for (int j = 0; j < 2; j++)
            wmma::fill_fragment(acc[i][j], 0.0f);

    for (int k0 = 0; k0 < K; k0 += BK) {
        // --- load A tile 128x16 (scalar, K-tail guarded) ---
        #pragma unroll
        for (int i = 0; i < 8; i++) {
            int idx = t + i * 256;
            int r = idx >> 4, c = idx & 15;
            float v = 0.f;
            if (k0 + c < K) v = A[(long long)(m0 + r) * K + (k0 + c)];
            float hi, lo; split_tf32(v, hi, lo);
            As_hi[r][c] = hi; As_lo[r][c] = lo;
        }
        // --- load B tile 16x64 (float4, K-tail guarded) ---
        {
            int r = t >> 4, c4 = t & 15;
            float4 v = make_float4(0.f, 0.f, 0.f, 0.f);
            if (k0 + r < K)
                v = *(const float4*)(Bm + (long long)(k0 + r) * Nc + n0 + c4 * 4);
            float hi, lo;
            split_tf32(v.x, hi, lo); Bs_hi[r][c4*4+0] = hi; Bs_lo[r][c4*4+0] = lo;
            split_tf32(v.y, hi, lo); Bs_hi[r][c4*4+1] = hi; Bs_lo[r][c4*4+1] = lo;
            split_tf32(v.z, hi, lo); Bs_hi[r][c4*4+2] = hi; Bs_lo[r][c4*4+2] = lo;
            split_tf32(v.w, hi, lo); Bs_hi[r][c4*4+3] = hi; Bs_lo[r][c4*4+3] = lo;
        }
        __syncthreads();

        #pragma unroll
        for (int ks = 0; ks < 2; ks++) {
            wmma::fragment<wmma::matrix_a, 16, 16, 8, wmma::precision::tf32, wmma::row_major> ah[2], al[2];
            wmma::fragment<wmma::matrix_b, 16, 16, 8, wmma::precision::tf32, wmma::row_major> bh[2], bl[2];
            #pragma unroll
            for (int i = 0; i < 2; i++) {
                wmma::load_matrix_sync(ah[i], &As_hi[wm + i * 16][ks * 8], BK);
                wmma::load_matrix_sync(al[i], &As_lo[wm + i * 16][ks * 8], BK);
            }
            #pragma unroll
            for (int j = 0; j < 2; j++) {
                wmma::load_matrix_sync(bh[j], &Bs_hi[ks * 8][wn + j * 16], BN);
                wmma::load_matrix_sync(bl[j], &Bs_lo[ks * 8][wn + j * 16], BN);
            }
            #pragma unroll
            for (int i = 0; i < 2; i++)
                #pragma unroll
                for (int j = 0; j < 2; j++) {
                    wmma::mma_sync(acc[i][j], ah[i], bl[j], acc[i][j]);
                    wmma::mma_sync(acc[i][j], al[i], bh[j], acc[i][j]);
                    wmma::mma_sync(acc[i][j], ah[i], bh[j], acc[i][j]);
                }
        }
        __syncthreads();
    }

    #pragma unroll
    for (int i = 0; i < 2; i++)
        #pragma unroll
        for (int j = 0; j < 2; j++)
            wmma::store_matrix_sync(&C[(long long)(m0 + wm + i * 16) * Nc + (n0 + wn + j * 16)],
                                    acc[i][j], Nc, wmma::mem_row_major);
}

// ---------------- attention coefficients: e1/e2 dot products ----------------
__global__ void attn_coef_kernel(const float* __restrict__ Wh,
                                 const float* __restrict__ a,
                                 float* __restrict__ e1, float* __restrict__ e2,
                                 int Of, int rowsPerHead, int totalRows) {
    int gw = (blockIdx.x * blockDim.x + threadIdx.x) >> 5;
    if (gw >= totalRows) return;
    int lane = threadIdx.x & 31;
    int h = gw / rowsPerHead;
    const float* w  = Wh + (size_t)gw * Of;
    const float* a1 = a + (size_t)h * 2 * Of;
    const float* a2 = a1 + Of;
    float s1 = 0.f, s2 = 0.f;
    for (int o = lane; o < Of; o += 32) {
        float v = w[o];
        s1 = fmaf(v, a1[o], s1);
        s2 = fmaf(v, a2[o], s2);
    }
    #pragma unroll
    for (int off = 16; off; off >>= 1) {
        s1 += __shfl_xor_sync(0xffffffffu, s1, off);
        s2 += __shfl_xor_sync(0xffffffffu, s2, off);
    }
    if (lane == 0) { e1[gw] = s1; e2[gw] = s2; }
}

// ---------------- masked leaky-relu softmax: one WARP per row of 256 ----------------
// Row layout: (HB, N). adj is (B,N,N): b = hb % cB, n = row % cN.
__global__ void softmax_kernel(const float* __restrict__ e1,
                               const float* __restrict__ e2,
                               const int* __restrict__ adj,
                               float* __restrict__ attn,
                               int totalRows) {
    int gw = (blockIdx.x * blockDim.x + threadIdx.x) >> 5;
    if (gw >= totalRows) return;
    int lane = threadIdx.x & 31;
    int hb = gw >> 8;           // row / cN
    int n  = gw & 255;
    int b  = hb & (cB - 1);     // cB = 32

    const int4*   adjRow = (const int4*)(adj + ((size_t)b * cN + n) * cN);
    const float4* e2Row  = (const float4*)(e2 + (size_t)hb * cN);
    float e1v = e1[gw];

    float v[8];
    float vmax = -INFINITY;
    #pragma unroll
    for (int jj = 0; jj < 2; jj++) {
        int i4 = lane + 32 * jj;
        int4   a4 = adjRow[i4];
        float4 e4 = e2Row[i4];
        const float* ep = (const float*)&e4;
        const int*   ap = (const int*)&a4;
        #pragma unroll
        for (int c = 0; c < 4; c++) {
            float x = e1v + ep[c];
            x = x > 0.f ? x : 0.2f * x;
            if (ap[c] <= 0) x = NEGV;
            v[jj * 4 + c] = x;
            vmax = fmaxf(vmax, x);
        }
    }
    #pragma unroll
    for (int off = 16; off; off >>= 1)
        vmax = fmaxf(vmax, __shfl_xor_sync(0xffffffffu, vmax, off));

    float s = 0.f;
    #pragma unroll
    for (int k = 0; k < 8; k++) { v[k] = expf(v[k] - vmax); s += v[k]; }
    #pragma unroll
    for (int off = 16; off; off >>= 1)
        s += __shfl_xor_sync(0xffffffffu, s, off);
    float inv = 1.f / s;

    float4* outRow = (float4*)(attn + (size_t)gw * cN);
    #pragma unroll
    for (int jj = 0; jj < 2; jj++) {
        int i4 = lane + 32 * jj;
        outRow[i4] = make_float4(v[jj*4+0]*inv, v[jj*4+1]*inv, v[jj*4+2]*inv, v[jj*4+3]*inv);
    }
}

// ---------------- head merge: elu + transpose (H,B,N,O)->(B,N,H*O) + mask (float4) ----------------
__global__ void head_merge_kernel(const float* __restrict__ mask) {
    int i4 = blockIdx.x * blockDim.x + threadIdx.x;
    if (i4 >= cH * cB * cN * cO / 4) return;
    int o4  = i4 & 63;            // cO/4 = 64
    int rem = i4 >> 6;
    int n   = rem & (cN - 1); rem >>= 8;
    int b   = rem & (cB - 1);
    int h   = rem >> 5;
    float4 val = ((const float4*)g_hHB)[i4];
    float mk = mask[b * cN + n];
    float* vp = (float*)&val;
    #pragma unroll
    for (int c = 0; c < 4; c++) {
        float v = vp[c];
        v = v > 0.f ? v : expm1f(v);
        vp[c] = v * mk;
    }
    ((float4*)g_h1)[((size_t)(b * cN + n)) * (cHO / 4) + h * (cO / 4) + o4] = val;
}

// ---------------- final: out = elu(tmp * mask) (float4) ----------------
__global__ void final_elu_kernel(const float* __restrict__ mask,
                                 float* __restrict__ out) {
    int i4 = blockIdx.x * blockDim.x + threadIdx.x;
    if (i4 >= cB * cN * cOUT / 4) return;
    float4 val = ((const float4*)g_tmp)[i4];
    float mk = mask[i4 >> 7];     // (cOUT/4) = 128
    float* vp = (float*)&val;
    #pragma unroll
    for (int c = 0; c < 4; c++) {
        float v = vp[c] * mk;
        vp[c] = v > 0.f ? v : expm1f(v);
    }
    ((float4*)out)[i4] = val;
}

// ---------------- launch ----------------
extern "C" void kernel_launch(void* const* d_in, const int* in_sizes, int n_in,
                              void* d_out, int out_size) {
    const int*   fea    = (const int*)  d_in[0];
    const int*   adj    = (const int*)  d_in[1];
    const float* mask   = (const float*)d_in[2];
    const float* embed  = (const float*)d_in[3];
    const float* Wheads = (const float*)d_in[4];
    const float* aheads = (const float*)d_in[5];
    const float* Wout   = (const float*)d_in[6];
    const float* aout   = (const float*)d_in[7];
    float* out = (float*)d_out;

    float *px, *pWh, *pe1, *pe2, *pattn, *phHB, *ph1, *pWh2, *pe1b, *pe2b, *pattn2, *ptmp;
    cudaGetSymbolAddress((void**)&px,     g_x);
    cudaGetSymbolAddress((void**)&pWh,    g_Wh);
    cudaGetSymbolAddress((void**)&pe1,    g_e1);
    cudaGetSymbolAddress((void**)&pe2,    g_e2);
    cudaGetSymbolAddress((void**)&pattn,  g_attn);
    cudaGetSymbolAddress((void**)&phHB,   g_hHB);
    cudaGetSymbolAddress((void**)&ph1,    g_h1);
    cudaGetSymbolAddress((void**)&pWh2,   g_Wh2);
    cudaGetSymbolAddress((void**)&pe1b,   g_e1b);
    cudaGetSymbolAddress((void**)&pe2b,   g_e2b);
    cudaGetSymbolAddress((void**)&pattn2, g_attn2);
    cudaGetSymbolAddress((void**)&ptmp,   g_tmp);

    // 1) embedding gather
    gather_kernel<<<(cB * cN * (cF / 4) + 255) / 256, 256>>>(fea, embed);

    // 2) Wh = x @ W_heads[h]   -> (H,B,N,O)
    gemm_tc_kernel<<<dim3(cO / 64, (cB * cN) / 128, cH), 256>>>(
        px, Wheads, pWh, cB * cN, cO, cF,
        0LL, (long long)cF * cO, (long long)cB * cN * cO);

    // 3) e1/e2 per (h,b,n)
    attn_coef_kernel<<<(cH * cB * cN * 32 + 255) / 256, 256>>>(
        pWh, aheads, pe1, pe2, cO, cB * cN, cH * cB * cN);

    // 4) masked leaky softmax -> attn (H,B,N,N)
    softmax_kernel<<<(cH * cB * cN * 32 + 255) / 256, 256>>>(pe1, pe2, adj, pattn, cH * cB * cN);

    // 5) hHB = attn @ Wh  (batched over H*B)
    gemm_tc_kernel<<<dim3(cO / 64, cN / 128, cH * cB), 256>>>(
        pattn, pWh, phHB, cN, cO, cN,
        (long long)cN * cN, (long long)cN * cO, (long long)cN * cO);

    // 6) elu + head-concat transpose + mask -> h1 (B,N,H*O)
    head_merge_kernel<<<(cH * cB * cN * cO / 4 + 255) / 256, 256>>>(mask);

    // 7) Wh2 = h1 @ W_out  -> (B,N,OUT)
    gemm_tc_kernel<<<dim3(cOUT / 64, (cB * cN) / 128, 1), 256>>>(
        ph1, Wout, pWh2, cB * cN, cOUT, cHO, 0LL, 0LL, 0LL);

    // 8) e1b/e2b per (b,n)
    attn_coef_kernel<<<(cB * cN * 32 + 255) / 256, 256>>>(
        pWh2, aout, pe1b, pe2b, cOUT, cB * cN, cB * cN);

    // 9) softmax -> attn2 (B,N,N)
    softmax_kernel<<<(cB * cN * 32 + 255) / 256, 256>>>(pe1b, pe2b, adj, pattn2, cB * cN);

    // 10) tmp = attn2 @ Wh2 (batched over B)
    gemm_tc_kernel<<<dim3(cOUT / 64, cN / 128, cB), 256>>>(
        pattn2, pWh2, ptmp, cN, cOUT, cN,
        (long long)cN * cN, (long long)cN * cOUT, (long long)cN * cOUT);

    // 11) out = elu(tmp * mask)
    final_elu_kernel<<<(cB * cN * cOUT / 4 + 255) / 256, 256>>>(mask, out);
}